// round 12
// baseline (speedup 1.0000x reference)
#include <cuda_runtime.h>

typedef unsigned long long ull;

#define NT2  1024
#define BPB  2
#define BATCH 256

// ---------------- transposed-weight scratch (device globals: allowed) -------
__device__ __align__(16) float g_wt1[96  * 1024];
__device__ __align__(16) float g_wt2[256 * 512];
__device__ __align__(16) float g_wt3[128 * 256];
__device__ __align__(16) float g_wt4[64  * 128];
__device__ __align__(16) float g_ft1[32  * 128];
__device__ __align__(16) float g_ft2[128 * 64];
__device__ __align__(16) float g_ft3[64  * 32];

// dynamic smem layout (floats):
//  zb   [0,      2048)   slice-0 partials               8 KB
//  pb   [2048,   9216)   slice 1..S-1 partials         28 KB
//  hA   [9216,  10240)   dup-packed activations (ull)   4 KB
//  hB   [10240, 11264)   dup-packed activations (ull)   4 KB
//  ws4  [11264, 19456)   g_wt4  (64x128)               32 KB
//  wf1  [19456, 23552)   g_ft1  (32x128)               16 KB
//  wf2  [23552, 31744)   g_ft2  (128x64)               32 KB
//  wf3  [31744, 33792)   g_ft3  (64x32)                 8 KB
#define OF_ZB   0
#define OF_PB   2048
#define OF_HA   9216
#define OF_HB   10240
#define OF_WS4  11264
#define OF_WF1  19456
#define OF_WF2  23552
#define OF_WF3  31744
#define SMEM_FLOATS 33792
#define SMEM_BYTES  (SMEM_FLOATS * 4)

// ---------------- tiled transpose of all 7 matrices ------------------------
__global__ void __launch_bounds__(256)
transpose_all_kernel(const float* __restrict__ w1i, const float* __restrict__ w2i,
                     const float* __restrict__ w3i, const float* __restrict__ w4i,
                     const float* __restrict__ f1w, const float* __restrict__ f2w,
                     const float* __restrict__ f3w)
{
    __shared__ float tile[32][33];
    int bid = blockIdx.x;
    const float* src; float* dst; int R, C, Cpad, tcN, lb;

    if      (bid < 96)  { src = w1i; dst = g_wt1; R = 1024; C = 87;  Cpad = 96;  tcN = 3; lb = bid;       }
    else if (bid < 224) { src = w2i; dst = g_wt2; R = 512;  C = 256; Cpad = 256; tcN = 8; lb = bid - 96;  }
    else if (bid < 256) { src = w3i; dst = g_wt3; R = 256;  C = 128; Cpad = 128; tcN = 4; lb = bid - 224; }
    else if (bid < 264) { src = w4i; dst = g_wt4; R = 128;  C = 64;  Cpad = 64;  tcN = 2; lb = bid - 256; }
    else if (bid < 268) { src = f1w; dst = g_ft1; R = 128;  C = 32;  Cpad = 32;  tcN = 1; lb = bid - 264; }
    else if (bid < 276) { src = f2w; dst = g_ft2; R = 64;   C = 128; Cpad = 128; tcN = 4; lb = bid - 268; }
    else                { src = f3w; dst = g_ft3; R = 32;   C = 64;  Cpad = 64;  tcN = 2; lb = bid - 276; }

    const int tr = lb / tcN, tc = lb % tcN;
    const int tx = threadIdx.x & 31, ty = threadIdx.x >> 5;

#pragma unroll
    for (int yy = 0; yy < 4; yy++) {
        int r = tr * 32 + ty + yy * 8;
        int c = tc * 32 + tx;
        tile[ty + yy * 8][tx] = (r < R && c < C) ? src[r * C + c] : 0.0f;
    }
    __syncthreads();
#pragma unroll
    for (int yy = 0; yy < 4; yy++) {
        int c = tc * 32 + ty + yy * 8;
        int r = tr * 32 + tx;
        if (r < R && c < Cpad) dst[c * R + r] = tile[tx][ty + yy * 8];
    }
}

// ---------------- packed fp32x2 helpers -------------------------------------
__device__ __forceinline__ ull pk2(float lo, float hi) {
    ull r; asm("mov.b64 %0, {%1, %2};" : "=l"(r) : "f"(lo), "f"(hi)); return r;
}
__device__ __forceinline__ void upk(ull v, float& lo, float& hi) {
    asm("mov.b64 {%0, %1}, %2;" : "=f"(lo), "=f"(hi) : "l"(v));
}
__device__ __forceinline__ ull ffma2(ull a, ull b, ull c) {
    ull d; asm("fma.rn.f32x2 %0, %1, %2, %3;" : "=l"(d) : "l"(a), "l"(b), "l"(c)); return d;
}
__device__ __forceinline__ float tanha(float x) {
    float y; asm("tanh.approx.f32 %0, %1;" : "=f"(y) : "f"(x)); return y;
}
__device__ __forceinline__ float fsig(float x) {
    return fmaf(0.5f, tanha(0.5f * x), 0.5f);
}

// cp.async 16B: global -> shared
__device__ __forceinline__ void cpa16(void* smem_dst, const void* gsrc) {
    unsigned sa = (unsigned)__cvta_generic_to_shared(smem_dst);
    asm volatile("cp.async.ca.shared.global [%0], [%1], 16;" :: "r"(sa), "l"(gsrc));
}

// ---------------- K-split dense: z partials into zb (slice0) / pb -----------
// WT is [DIN][ROWS]. WS=true -> WT points to shared memory (plain LDS loads).
template<int ROWS, int DIN, int VEC, int S, int U, bool WS>
__device__ __forceinline__ void dense_ks(
    const float* __restrict__ WT, const float* __restrict__ bias,
    const ull* __restrict__ xin, int xstride,          // dup-packed {v,v}
    float* __restrict__ zb, float* __restrict__ pb, int tid)
{
    constexpr int ACTIVE = ROWS / VEC;
    constexpr int KS = DIN / S;
    static_assert(ACTIVE * S <= NT2, "thread layout");
    static_assert((KS % U == 0 && KS > U && U % 2 == 0) || KS < 32, "slice shape");
    if (tid >= ACTIVE * S) return;
    const int s  = tid / ACTIVE;
    const int r  = tid - s * ACTIVE;
    const int kb = s * KS;
    float* outp = (s == 0) ? zb : (pb + (s - 1) * (ROWS * BPB));
    const float* xf = reinterpret_cast<const float*>(xin);
    const ulonglong2* x2p = reinterpret_cast<const ulonglong2*>(xin);

    if constexpr (VEC == 4) {
        constexpr int W4 = ROWS / 4;
        const int r0 = r * 4;
        const ulonglong2* base = reinterpret_cast<const ulonglong2*>(WT) + r;
        ull acc[BPB][2];
        {
            ull blo = 0ull, bhi = 0ull;
            if (s == 0) {
                blo = pk2(__ldg(bias + r0),     __ldg(bias + r0 + 1));
                bhi = pk2(__ldg(bias + r0 + 2), __ldg(bias + r0 + 3));
            }
#pragma unroll
            for (int b = 0; b < BPB; b++) { acc[b][0] = blo; acc[b][1] = bhi; }
        }
        ulonglong2 buf[U];
#pragma unroll
        for (int u = 0; u < U; u++)
            buf[u] = WS ? base[(kb + u) * W4] : __ldg(base + (kb + u) * W4);
        for (int k0 = 0; k0 < KS - U; k0 += U) {
#pragma unroll
            for (int u2 = 0; u2 < U / 2; u2++) {
                ull wlo0 = buf[2*u2].x,   whi0 = buf[2*u2].y;
                ull wlo1 = buf[2*u2+1].x, whi1 = buf[2*u2+1].y;
#pragma unroll
                for (int b = 0; b < BPB; b++) {
                    ulonglong2 xp = x2p[(b * xstride + kb + k0) / 2 + u2]; // 2 k's
                    acc[b][0] = ffma2(wlo0, xp.x, acc[b][0]);
                    acc[b][1] = ffma2(whi0, xp.x, acc[b][1]);
                    acc[b][0] = ffma2(wlo1, xp.y, acc[b][0]);
                    acc[b][1] = ffma2(whi1, xp.y, acc[b][1]);
                }
                buf[2*u2]   = WS ? base[(kb + k0 + U + 2*u2)     * W4]
                                 : __ldg(base + (kb + k0 + U + 2*u2)     * W4);
                buf[2*u2+1] = WS ? base[(kb + k0 + U + 2*u2 + 1) * W4]
                                 : __ldg(base + (kb + k0 + U + 2*u2 + 1) * W4);
            }
        }
#pragma unroll
        for (int u2 = 0; u2 < U / 2; u2++) {
            ull wlo0 = buf[2*u2].x,   whi0 = buf[2*u2].y;
            ull wlo1 = buf[2*u2+1].x, whi1 = buf[2*u2+1].y;
#pragma unroll
            for (int b = 0; b < BPB; b++) {
                ulonglong2 xp = x2p[(b * xstride + kb + (KS - U)) / 2 + u2];
                acc[b][0] = ffma2(wlo0, xp.x, acc[b][0]);
                acc[b][1] = ffma2(whi0, xp.x, acc[b][1]);
                acc[b][0] = ffma2(wlo1, xp.y, acc[b][0]);
                acc[b][1] = ffma2(whi1, xp.y, acc[b][1]);
            }
        }
#pragma unroll
        for (int b = 0; b < BPB; b++) {
            float l0, h0, l1, h1;
            upk(acc[b][0], l0, h0); upk(acc[b][1], l1, h1);
            outp[b * ROWS + r0]     = l0;
            outp[b * ROWS + r0 + 1] = h0;
            outp[b * ROWS + r0 + 2] = l1;
            outp[b * ROWS + r0 + 3] = h1;
        }
    } else if constexpr (VEC == 2) {
        constexpr int W2 = ROWS / 2;
        const int r0 = r * 2;
        const ull* base = reinterpret_cast<const ull*>(WT) + r;
        ull acc[BPB];
        ull bb = (s == 0) ? pk2(__ldg(bias + r0), __ldg(bias + r0 + 1)) : 0ull;
#pragma unroll
        for (int b = 0; b < BPB; b++) acc[b] = bb;
        ull buf[U];
#pragma unroll
        for (int u = 0; u < U; u++)
            buf[u] = WS ? base[(kb + u) * W2] : __ldg(base + (kb + u) * W2);
        for (int k0 = 0; k0 < KS - U; k0 += U) {
#pragma unroll
            for (int u2 = 0; u2 < U / 2; u2++) {
                ull w0 = buf[2*u2], w1 = buf[2*u2+1];
#pragma unroll
                for (int b = 0; b < BPB; b++) {
                    ulonglong2 xp = x2p[(b * xstride + kb + k0) / 2 + u2];
                    acc[b] = ffma2(w0, xp.x, acc[b]);
                    acc[b] = ffma2(w1, xp.y, acc[b]);
                }
                buf[2*u2]   = WS ? base[(kb + k0 + U + 2*u2)     * W2]
                                 : __ldg(base + (kb + k0 + U + 2*u2)     * W2);
                buf[2*u2+1] = WS ? base[(kb + k0 + U + 2*u2 + 1) * W2]
                                 : __ldg(base + (kb + k0 + U + 2*u2 + 1) * W2);
            }
        }
#pragma unroll
        for (int u2 = 0; u2 < U / 2; u2++) {
            ull w0 = buf[2*u2], w1 = buf[2*u2+1];
#pragma unroll
            for (int b = 0; b < BPB; b++) {
                ulonglong2 xp = x2p[(b * xstride + kb + (KS - U)) / 2 + u2];
                acc[b] = ffma2(w0, xp.x, acc[b]);
                acc[b] = ffma2(w1, xp.y, acc[b]);
            }
        }
#pragma unroll
        for (int b = 0; b < BPB; b++) {
            float lo, hi; upk(acc[b], lo, hi);
            outp[b * ROWS + r0]     = lo;
            outp[b * ROWS + r0 + 1] = hi;
        }
    } else {  // VEC == 1, scalar rows (short KS only)
        float acc[BPB];
        float bv = (s == 0) ? __ldg(bias + r) : 0.0f;
#pragma unroll
        for (int b = 0; b < BPB; b++) acc[b] = bv;
#pragma unroll
        for (int k = 0; k < KS; k++) {
            float w = WS ? WT[(kb + k) * ROWS + r] : __ldg(WT + (kb + k) * ROWS + r);
#pragma unroll
            for (int b = 0; b < BPB; b++)
                acc[b] = fmaf(w, xf[2 * (b * xstride + kb + k)], acc[b]);
        }
#pragma unroll
        for (int b = 0; b < BPB; b++) outp[b * ROWS + r] = acc[b];
    }
}

// sum S partials, LSTM single-step combine (h0=c0=0) + outer tanh, dup-pack
template<int H, int S>
__device__ __forceinline__ void lstm_combine(
    const float* __restrict__ zb, const float* __restrict__ pb,
    ull* __restrict__ hd, int tid)
{
    constexpr int ROWS = 4 * H;
    for (int idx = tid; idx < H * BPB; idx += NT2) {
        int b = idx / H, j = idx - b * H;
        float zi = zb[b * ROWS + j];
        float zg = zb[b * ROWS + 2 * H + j];
        float zo = zb[b * ROWS + 3 * H + j];
#pragma unroll
        for (int s = 1; s < S; s++) {
            const float* p = pb + (s - 1) * (ROWS * BPB) + b * ROWS;
            zi += p[j]; zg += p[2 * H + j]; zo += p[3 * H + j];
        }
        float c = fsig(zi) * tanha(zg);
        float h = tanha(fsig(zo) * tanha(c));
        hd[b * 256 + j] = pk2(h, h);
    }
}

// sum S partials + relu, dup-pack into hd (stride 256)
template<int ROWS, int S>
__device__ __forceinline__ void relu_combine(
    const float* __restrict__ zb, const float* __restrict__ pb,
    ull* __restrict__ hd, int tid)
{
    for (int idx = tid; idx < ROWS * BPB; idx += NT2) {
        int b = idx / ROWS, j = idx - b * ROWS;
        float v = zb[b * ROWS + j];
#pragma unroll
        for (int s = 1; s < S; s++)
            v += pb[(s - 1) * (ROWS * BPB) + b * ROWS + j];
        v = fmaxf(v, 0.0f);
        hd[b * 256 + j] = pk2(v, v);
    }
}

__global__ void __launch_bounds__(NT2, 1)
rnn_fwd_kernel(
    const float* __restrict__ x,
    const float* __restrict__ b1, const float* __restrict__ b2,
    const float* __restrict__ b3, const float* __restrict__ b4,
    const float* __restrict__ f1b, const float* __restrict__ f2b,
    const float* __restrict__ f3b,
    const float* __restrict__ f4w, const float* __restrict__ f4b,
    float* __restrict__ out)
{
    extern __shared__ __align__(16) float smem[];
    float* zb  = smem + OF_ZB;
    float* pb  = smem + OF_PB;
    ull*   hA  = reinterpret_cast<ull*>(smem + OF_HA);
    ull*   hB  = reinterpret_cast<ull*>(smem + OF_HB);
    float* ws4 = smem + OF_WS4;
    float* wf1 = smem + OF_WF1;
    float* wf2 = smem + OF_WF2;
    float* wf3 = smem + OF_WF3;

    ull* xd = hB;                      // x staging lives in hB until L1 dense done

    const int tid = threadIdx.x;
    const int b0  = blockIdx.x * BPB;

    // ---- stage small-layer weights into smem via cp.async (overlapped) ----
    {
        // wt4: 8192 floats = 2048 x 16B
        for (int i = tid; i < 2048; i += NT2)
            cpa16(ws4 + i * 4, g_wt4 + i * 4);
        // ft1: 4096 floats = 1024 x 16B
        for (int i = tid; i < 1024; i += NT2)
            cpa16(wf1 + i * 4, g_ft1 + i * 4);
        // ft2: 8192 floats = 2048 x 16B
        for (int i = tid; i < 2048; i += NT2)
            cpa16(wf2 + i * 4, g_ft2 + i * 4);
        // ft3: 2048 floats = 512 x 16B
        for (int i = tid; i < 512; i += NT2)
            cpa16(wf3 + i * 4, g_ft3 + i * 4);
        asm volatile("cp.async.commit_group;");
    }

    // x is [T=1024, B=256, F=87]; need only t=0; dup-pack, zero-pad K to 96
    for (int i = tid; i < 96 * BPB; i += NT2) {
        int p = i / 96, f = i - p * 96;
        float v = (f < 87) ? __ldg(x + (b0 + p) * 87 + f) : 0.0f;
        xd[p * 96 + f] = pk2(v, v);
    }
    __syncthreads();

    // LSTM1: 87(->96) -> 256   rows=1024, VEC4, S=4, KS=24, U=8  (1024 thr)
    dense_ks<1024, 96, 4, 4, 8, false>(g_wt1, b1, xd, 96, zb, pb, tid);
    __syncthreads();
    lstm_combine<256, 4>(zb, pb, hA, tid);
    __syncthreads();

    // LSTM2: 256 -> 128        rows=512, VEC4, S=8, KS=32, U=8   (1024 thr)
    dense_ks<512, 256, 4, 8, 8, false>(g_wt2, b2, hA, 256, zb, pb, tid);
    __syncthreads();
    lstm_combine<128, 8>(zb, pb, hB, tid);
    __syncthreads();

    // LSTM3: 128 -> 64         rows=256, VEC2, S=8, KS=16, U=8   (1024 thr)
    dense_ks<256, 128, 2, 8, 8, false>(g_wt3, b3, hB, 256, zb, pb, tid);
    asm volatile("cp.async.wait_group 0;" ::: "memory");   // smem weights ready
    __syncthreads();
    lstm_combine<64, 8>(zb, pb, hA, tid);
    __syncthreads();

    // LSTM4: 64 -> 32          rows=128, VEC1, S=8, KS=8, SMEM weights
    dense_ks<128, 64, 1, 8, 4, true>(ws4, b4, hA, 256, zb, pb, tid);
    __syncthreads();
    lstm_combine<32, 8>(zb, pb, hB, tid);
    __syncthreads();

    // FC1: 32 -> 128 relu      rows=128, VEC1, S=8, KS=4, SMEM weights
    dense_ks<128, 32, 1, 8, 4, true>(wf1, f1b, hB, 256, zb, pb, tid);
    __syncthreads();
    relu_combine<128, 8>(zb, pb, hA, tid);
    __syncthreads();

    // FC2: 128 -> 64 relu      rows=64, VEC1, S=16, KS=8, SMEM weights
    dense_ks<64, 128, 1, 16, 4, true>(wf2, f2b, hA, 256, zb, pb, tid);
    __syncthreads();
    relu_combine<64, 16>(zb, pb, hB, tid);
    __syncthreads();

    // FC3: 64 -> 32 relu       rows=32, VEC1, S=16, KS=4, SMEM weights
    dense_ks<32, 64, 1, 16, 4, true>(wf3, f3b, hB, 256, zb, pb, tid);
    __syncthreads();
    relu_combine<32, 16>(zb, pb, hA, tid);
    __syncthreads();

    // FC4: 32 -> 3, warp-parallel: warp w handles (b, r); lane = k. fp32 weights.
    if (tid < 3 * BPB * 32) {
        int w    = tid >> 5;          // 0..5
        int lane = tid & 31;
        int b    = w / 3, r = w - b * 3;
        float lo, hi; upk(hA[b * 256 + lane], lo, hi);
        float v = __ldg(f4w + r * 32 + lane) * lo;
#pragma unroll
        for (int off = 16; off > 0; off >>= 1)
            v += __shfl_xor_sync(0xFFFFFFFF, v, off);
        if (lane == 0) out[(b0 + b) * 3 + r] = v + __ldg(f4b + r);
    }
}

extern "C" void kernel_launch(void* const* d_in, const int* in_sizes, int n_in,
                              void* d_out, int out_size)
{
    const float* x   = (const float*)d_in[0];
    const float* w1i = (const float*)d_in[1];
    const float* b1  = (const float*)d_in[3];
    const float* w2i = (const float*)d_in[4];
    const float* b2  = (const float*)d_in[6];
    const float* w3i = (const float*)d_in[7];
    const float* b3  = (const float*)d_in[9];
    const float* w4i = (const float*)d_in[10];
    const float* b4  = (const float*)d_in[12];
    const float* f1w = (const float*)d_in[13];
    const float* f1b = (const float*)d_in[14];
    const float* f2w = (const float*)d_in[15];
    const float* f2b = (const float*)d_in[16];
    const float* f3w = (const float*)d_in[17];
    const float* f3b = (const float*)d_in[18];
    const float* f4w = (const float*)d_in[19];
    const float* f4b = (const float*)d_in[20];
    float* out = (float*)d_out;

    static int smem_set = 0;
    if (!smem_set) {
        cudaFuncSetAttribute(rnn_fwd_kernel,
                             cudaFuncAttributeMaxDynamicSharedMemorySize, SMEM_BYTES);
        smem_set = 1;
    }

    transpose_all_kernel<<<278, 256>>>(w1i, w2i, w3i, w4i, f1w, f2w, f3w);
    rnn_fwd_kernel<<<BATCH / BPB, NT2, SMEM_BYTES>>>(
        x, b1, b2, b3, b4, f1b, f2b, f3b, f4w, f4b, out);
}

// round 13
// speedup vs baseline: 1.1540x; 1.1540x over previous
#include <cuda_runtime.h>

typedef unsigned long long ull;

#define NT2  1024
#define BPB  2
#define BATCH 256

// ---------------- transposed-weight scratch (device globals: allowed) -------
// LSTM weights stored WITHOUT the dead forget-gate rows: [DIN][3H] (i,g,o)
__device__ __align__(16) float g_wt1[96  * 768];
__device__ __align__(16) float g_wt2[256 * 384];
__device__ __align__(16) float g_wt3[128 * 192];
__device__ __align__(16) float g_wt4[64  * 96];
__device__ __align__(16) float g_ft1[32  * 128];
__device__ __align__(16) float g_ft2[128 * 64];
__device__ __align__(16) float g_ft3[64  * 32];

// ---------------- tiled transpose of all 7 matrices (f-gate rows dropped) ---
__global__ void __launch_bounds__(256)
transpose_all_kernel(const float* __restrict__ w1i, const float* __restrict__ w2i,
                     const float* __restrict__ w3i, const float* __restrict__ w4i,
                     const float* __restrict__ f1w, const float* __restrict__ f2w,
                     const float* __restrict__ f3w)
{
    __shared__ float tile[32][33];
    int bid = blockIdx.x;
    const float* src; float* dst; int R, C, Cpad, tcN, lb, H;

    if      (bid < 96)  { src = w1i; dst = g_wt1; R = 1024; C = 87;  Cpad = 96;  tcN = 3; lb = bid;       H = 256; }
    else if (bid < 224) { src = w2i; dst = g_wt2; R = 512;  C = 256; Cpad = 256; tcN = 8; lb = bid - 96;  H = 128; }
    else if (bid < 256) { src = w3i; dst = g_wt3; R = 256;  C = 128; Cpad = 128; tcN = 4; lb = bid - 224; H = 64;  }
    else if (bid < 264) { src = w4i; dst = g_wt4; R = 128;  C = 64;  Cpad = 64;  tcN = 2; lb = bid - 256; H = 32;  }
    else if (bid < 268) { src = f1w; dst = g_ft1; R = 128;  C = 32;  Cpad = 32;  tcN = 1; lb = bid - 264; H = 0;   }
    else if (bid < 276) { src = f2w; dst = g_ft2; R = 64;   C = 128; Cpad = 128; tcN = 4; lb = bid - 268; H = 0;   }
    else                { src = f3w; dst = g_ft3; R = 32;   C = 64;  Cpad = 64;  tcN = 2; lb = bid - 276; H = 0;   }

    const int Rd = (H > 0) ? (R - H) : R;   // dst row count (3H for LSTM)
    const int tr = lb / tcN, tc = lb % tcN;
    const int tx = threadIdx.x & 31, ty = threadIdx.x >> 5;

#pragma unroll
    for (int yy = 0; yy < 4; yy++) {
        int r = tr * 32 + ty + yy * 8;
        int c = tc * 32 + tx;
        tile[ty + yy * 8][tx] = (r < R && c < C) ? src[r * C + c] : 0.0f;
    }
    __syncthreads();
#pragma unroll
    for (int yy = 0; yy < 4; yy++) {
        int c  = tc * 32 + ty + yy * 8;
        int rs = tr * 32 + tx;              // source row
        if (rs < R && c < Cpad) {
            int rd;
            if (H > 0) {
                if (rs >= H && rs < 2 * H) continue;       // skip f-gate rows
                rd = (rs < H) ? rs : (rs - H);             // i stays, g/o shift down
            } else rd = rs;
            dst[c * Rd + rd] = tile[tx][ty + yy * 8];
        }
    }
}

// ---------------- packed fp32x2 helpers -------------------------------------
__device__ __forceinline__ ull pk2(float lo, float hi) {
    ull r; asm("mov.b64 %0, {%1, %2};" : "=l"(r) : "f"(lo), "f"(hi)); return r;
}
__device__ __forceinline__ void upk(ull v, float& lo, float& hi) {
    asm("mov.b64 {%0, %1}, %2;" : "=f"(lo), "=f"(hi) : "l"(v));
}
__device__ __forceinline__ ull ffma2(ull a, ull b, ull c) {
    ull d; asm("fma.rn.f32x2 %0, %1, %2, %3;" : "=l"(d) : "l"(a), "l"(b), "l"(c)); return d;
}
__device__ __forceinline__ float tanha(float x) {
    float y; asm("tanh.approx.f32 %0, %1;" : "=f"(y) : "f"(x)); return y;
}
__device__ __forceinline__ float fsig(float x) {
    return fmaf(0.5f, tanha(0.5f * x), 0.5f);
}

// ---------------- K-split dense: z partials into zb (slice0) / pb -----------
// WT is [DIN][ROWS]. slice s = tid/ACTIVE handles k in [s*KS,(s+1)*KS);
// lane r = tid%ACTIVE handles VEC consecutive rows. x is dup-packed {v,v}.
// BIASF: bias has f-gate rows removed? For LSTM layers bias still has 4H
// entries (i,f,g,o) — map via BH (H, 0 for FC): row j -> bias idx j<H? j : j+H.
template<int ROWS, int DIN, int VEC, int S, int U, int BH>
__device__ __forceinline__ void dense_ks(
    const float* __restrict__ WT, const float* __restrict__ bias,
    const ull* __restrict__ xin, int xstride,          // dup-packed {v,v}
    float* __restrict__ zb, float* __restrict__ pb, int tid)
{
    constexpr int ACTIVE = ROWS / VEC;
    constexpr int KS = DIN / S;
    static_assert(ACTIVE * S <= NT2, "thread layout");
    static_assert((KS % U == 0 && KS > U && U % 2 == 0) || KS < 32, "slice shape");
    if (tid >= ACTIVE * S) return;
    const int s  = tid / ACTIVE;
    const int r  = tid - s * ACTIVE;
    const int kb = s * KS;
    float* outp = (s == 0) ? zb : (pb + (s - 1) * (ROWS * BPB));
    const float* xf = reinterpret_cast<const float*>(xin);
    const ulonglong2* x2p = reinterpret_cast<const ulonglong2*>(xin);

    // bias row remap (skip f rows): dense row j corresponds to bias index
    auto bidx = [](int j) { return (BH > 0 && j >= BH) ? j + BH : j; };

    if constexpr (VEC == 4) {
        constexpr int W4 = ROWS / 4;
        const int r0 = r * 4;
        const ulonglong2* base = reinterpret_cast<const ulonglong2*>(WT) + r;
        ull acc[BPB][2];
        {
            ull blo = 0ull, bhi = 0ull;
            if (s == 0) {
                blo = pk2(__ldg(bias + bidx(r0)),     __ldg(bias + bidx(r0 + 1)));
                bhi = pk2(__ldg(bias + bidx(r0 + 2)), __ldg(bias + bidx(r0 + 3)));
            }
#pragma unroll
            for (int b = 0; b < BPB; b++) { acc[b][0] = blo; acc[b][1] = bhi; }
        }
        ulonglong2 buf[U];
#pragma unroll
        for (int u = 0; u < U; u++) buf[u] = __ldg(base + (kb + u) * W4);
        for (int k0 = 0; k0 < KS - U; k0 += U) {
#pragma unroll
            for (int u2 = 0; u2 < U / 2; u2++) {
                ull wlo0 = buf[2*u2].x,   whi0 = buf[2*u2].y;
                ull wlo1 = buf[2*u2+1].x, whi1 = buf[2*u2+1].y;
#pragma unroll
                for (int b = 0; b < BPB; b++) {
                    ulonglong2 xp = x2p[(b * xstride + kb + k0) / 2 + u2]; // 2 k's
                    acc[b][0] = ffma2(wlo0, xp.x, acc[b][0]);
                    acc[b][1] = ffma2(whi0, xp.x, acc[b][1]);
                    acc[b][0] = ffma2(wlo1, xp.y, acc[b][0]);
                    acc[b][1] = ffma2(whi1, xp.y, acc[b][1]);
                }
                buf[2*u2]   = __ldg(base + (kb + k0 + U + 2*u2)     * W4);
                buf[2*u2+1] = __ldg(base + (kb + k0 + U + 2*u2 + 1) * W4);
            }
        }
#pragma unroll
        for (int u2 = 0; u2 < U / 2; u2++) {
            ull wlo0 = buf[2*u2].x,   whi0 = buf[2*u2].y;
            ull wlo1 = buf[2*u2+1].x, whi1 = buf[2*u2+1].y;
#pragma unroll
            for (int b = 0; b < BPB; b++) {
                ulonglong2 xp = x2p[(b * xstride + kb + (KS - U)) / 2 + u2];
                acc[b][0] = ffma2(wlo0, xp.x, acc[b][0]);
                acc[b][1] = ffma2(whi0, xp.x, acc[b][1]);
                acc[b][0] = ffma2(wlo1, xp.y, acc[b][0]);
                acc[b][1] = ffma2(whi1, xp.y, acc[b][1]);
            }
        }
#pragma unroll
        for (int b = 0; b < BPB; b++) {
            float l0, h0, l1, h1;
            upk(acc[b][0], l0, h0); upk(acc[b][1], l1, h1);
            outp[b * ROWS + r0]     = l0;
            outp[b * ROWS + r0 + 1] = h0;
            outp[b * ROWS + r0 + 2] = l1;
            outp[b * ROWS + r0 + 3] = h1;
        }
    } else if constexpr (VEC == 2) {
        constexpr int W2 = ROWS / 2;
        const int r0 = r * 2;
        const ull* base = reinterpret_cast<const ull*>(WT) + r;
        ull acc[BPB];
        ull bb = (s == 0) ? pk2(__ldg(bias + bidx(r0)), __ldg(bias + bidx(r0 + 1))) : 0ull;
#pragma unroll
        for (int b = 0; b < BPB; b++) acc[b] = bb;
        ull buf[U];
#pragma unroll
        for (int u = 0; u < U; u++) buf[u] = __ldg(base + (kb + u) * W2);
        for (int k0 = 0; k0 < KS - U; k0 += U) {
#pragma unroll
            for (int u2 = 0; u2 < U / 2; u2++) {
                ull w0 = buf[2*u2], w1 = buf[2*u2+1];
#pragma unroll
                for (int b = 0; b < BPB; b++) {
                    ulonglong2 xp = x2p[(b * xstride + kb + k0) / 2 + u2];
                    acc[b] = ffma2(w0, xp.x, acc[b]);
                    acc[b] = ffma2(w1, xp.y, acc[b]);
                }
                buf[2*u2]   = __ldg(base + (kb + k0 + U + 2*u2)     * W2);
                buf[2*u2+1] = __ldg(base + (kb + k0 + U + 2*u2 + 1) * W2);
            }
        }
#pragma unroll
        for (int u2 = 0; u2 < U / 2; u2++) {
            ull w0 = buf[2*u2], w1 = buf[2*u2+1];
#pragma unroll
            for (int b = 0; b < BPB; b++) {
                ulonglong2 xp = x2p[(b * xstride + kb + (KS - U)) / 2 + u2];
                acc[b] = ffma2(w0, xp.x, acc[b]);
                acc[b] = ffma2(w1, xp.y, acc[b]);
            }
        }
#pragma unroll
        for (int b = 0; b < BPB; b++) {
            float lo, hi; upk(acc[b], lo, hi);
            outp[b * ROWS + r0]     = lo;
            outp[b * ROWS + r0 + 1] = hi;
        }
    } else {  // VEC == 1, scalar rows (short KS only)
        float acc[BPB];
        float bv = (s == 0) ? __ldg(bias + bidx(r)) : 0.0f;
#pragma unroll
        for (int b = 0; b < BPB; b++) acc[b] = bv;
#pragma unroll
        for (int k = 0; k < KS; k++) {
            float w = __ldg(WT + (kb + k) * ROWS + r);
#pragma unroll
            for (int b = 0; b < BPB; b++)
                acc[b] = fmaf(w, xf[2 * (b * xstride + kb + k)], acc[b]);
        }
#pragma unroll
        for (int b = 0; b < BPB; b++) outp[b * ROWS + r] = acc[b];
    }
}

// sum S partials, LSTM combine from (h0=c0=0) + outer tanh, dup-pack.
// z layout: ROWS = 3H, gates at {j, H+j, 2H+j} = {i, g, o}.
template<int H, int S>
__device__ __forceinline__ void lstm_combine(
    const float* __restrict__ zb, const float* __restrict__ pb,
    ull* __restrict__ hd, int tid)
{
    constexpr int ROWS = 3 * H;
    for (int idx = tid; idx < H * BPB; idx += NT2) {
        int b = idx / H, j = idx - b * H;
        float zi = zb[b * ROWS + j];
        float zg = zb[b * ROWS + H + j];
        float zo = zb[b * ROWS + 2 * H + j];
#pragma unroll
        for (int s = 1; s < S; s++) {
            const float* p = pb + (s - 1) * (ROWS * BPB) + b * ROWS;
            zi += p[j]; zg += p[H + j]; zo += p[2 * H + j];
        }
        float c = fsig(zi) * tanha(zg);
        float h = tanha(fsig(zo) * tanha(c));
        hd[b * 256 + j] = pk2(h, h);
    }
}

// sum S partials + relu, dup-pack into hd (stride 256)
template<int ROWS, int S>
__device__ __forceinline__ void relu_combine(
    const float* __restrict__ zb, const float* __restrict__ pb,
    ull* __restrict__ hd, int tid)
{
    for (int idx = tid; idx < ROWS * BPB; idx += NT2) {
        int b = idx / ROWS, j = idx - b * ROWS;
        float v = zb[b * ROWS + j];
#pragma unroll
        for (int s = 1; s < S; s++)
            v += pb[(s - 1) * (ROWS * BPB) + b * ROWS + j];
        v = fmaxf(v, 0.0f);
        hd[b * 256 + j] = pk2(v, v);
    }
}

__global__ void __launch_bounds__(NT2, 1)
rnn_fwd_kernel(
    const float* __restrict__ x,
    const float* __restrict__ b1, const float* __restrict__ b2,
    const float* __restrict__ b3, const float* __restrict__ b4,
    const float* __restrict__ f1b, const float* __restrict__ f2b,
    const float* __restrict__ f3b,
    const float* __restrict__ f4w, const float* __restrict__ f4b,
    float* __restrict__ out)
{
    __shared__ float zb[BPB * 768];                     //  6 KB  slice-0 partials
    __shared__ float pb[7 * 1024];                      // 28 KB  slice 1..S-1 partials
    __shared__ __align__(16) ull hA[BPB * 256];         //  4 KB  dup-packed activations
    __shared__ __align__(16) ull hB[BPB * 256];         //  4 KB  (xd overlaid)

    ull* xd = hB;                      // x staging lives in hB until L1 dense done

    const int tid = threadIdx.x;
    const int b0  = blockIdx.x * BPB;

    // x is [T=1024, B=256, F=87]; need only t=0; dup-pack, zero-pad K to 96
    for (int i = tid; i < 96 * BPB; i += NT2) {
        int p = i / 96, f = i - p * 96;
        float v = (f < 87) ? __ldg(x + (b0 + p) * 87 + f) : 0.0f;
        xd[p * 96 + f] = pk2(v, v);
    }
    __syncthreads();

    // LSTM1: 87(->96) -> 256   rows=768 (i,g,o), VEC4, S=4, KS=24, U=8 (768 thr)
    dense_ks<768, 96, 4, 4, 8, 256>(g_wt1, b1, xd, 96, zb, pb, tid);
    __syncthreads();
    lstm_combine<256, 4>(zb, pb, hA, tid);
    __syncthreads();

    // LSTM2: 256 -> 128        rows=384, VEC4, S=8, KS=32, U=8 (768 thr)
    dense_ks<384, 256, 4, 8, 8, 128>(g_wt2, b2, hA, 256, zb, pb, tid);
    __syncthreads();
    lstm_combine<128, 8>(zb, pb, hB, tid);
    __syncthreads();

    // LSTM3: 128 -> 64         rows=192, VEC2, S=8, KS=16, U=8 (768 thr)
    dense_ks<192, 128, 2, 8, 8, 64>(g_wt3, b3, hB, 256, zb, pb, tid);
    __syncthreads();
    lstm_combine<64, 8>(zb, pb, hA, tid);
    __syncthreads();

    // LSTM4: 64 -> 32          rows=96, VEC1, S=8, KS=8 (short) (768 thr)
    dense_ks<96, 64, 1, 8, 4, 32>(g_wt4, b4, hA, 256, zb, pb, tid);
    __syncthreads();
    lstm_combine<32, 8>(zb, pb, hB, tid);
    __syncthreads();

    // FC1: 32 -> 128 relu      rows=128, VEC1, S=8, KS=4 (short) (1024 thr)
    dense_ks<128, 32, 1, 8, 4, 0>(g_ft1, f1b, hB, 256, zb, pb, tid);
    __syncthreads();
    relu_combine<128, 8>(zb, pb, hA, tid);
    __syncthreads();

    // FC2: 128 -> 64 relu      rows=64, VEC1, S=16, KS=8 (short) (1024 thr)
    dense_ks<64, 128, 1, 16, 4, 0>(g_ft2, f2b, hA, 256, zb, pb, tid);
    __syncthreads();
    relu_combine<64, 16>(zb, pb, hB, tid);
    __syncthreads();

    // FC3: 64 -> 32 relu       rows=32, VEC1, S=16, KS=4 (short) (512 thr)
    dense_ks<32, 64, 1, 16, 4, 0>(g_ft3, f3b, hB, 256, zb, pb, tid);
    __syncthreads();
    relu_combine<32, 16>(zb, pb, hA, tid);
    __syncthreads();

    // FC4: 32 -> 3, warp-parallel: warp w handles (b, r); lane = k. fp32 weights.
    if (tid < 3 * BPB * 32) {
        int w    = tid >> 5;          // 0..5
        int lane = tid & 31;
        int b    = w / 3, r = w - b * 3;
        float lo, hi; upk(hA[b * 256 + lane], lo, hi);
        float v = __ldg(f4w + r * 32 + lane) * lo;
#pragma unroll
        for (int off = 16; off > 0; off >>= 1)
            v += __shfl_xor_sync(0xFFFFFFFF, v, off);
        if (lane == 0) out[(b0 + b) * 3 + r] = v + __ldg(f4b + r);
    }
}

extern "C" void kernel_launch(void* const* d_in, const int* in_sizes, int n_in,
                              void* d_out, int out_size)
{
    const float* x   = (const float*)d_in[0];
    const float* w1i = (const float*)d_in[1];
    const float* b1  = (const float*)d_in[3];
    const float* w2i = (const float*)d_in[4];
    const float* b2  = (const float*)d_in[6];
    const float* w3i = (const float*)d_in[7];
    const float* b3  = (const float*)d_in[9];
    const float* w4i = (const float*)d_in[10];
    const float* b4  = (const float*)d_in[12];
    const float* f1w = (const float*)d_in[13];
    const float* f1b = (const float*)d_in[14];
    const float* f2w = (const float*)d_in[15];
    const float* f2b = (const float*)d_in[16];
    const float* f3w = (const float*)d_in[17];
    const float* f3b = (const float*)d_in[18];
    const float* f4w = (const float*)d_in[19];
    const float* f4b = (const float*)d_in[20];
    float* out = (float*)d_out;

    transpose_all_kernel<<<278, 256>>>(w1i, w2i, w3i, w4i, f1w, f2w, f3w);
    rnn_fwd_kernel<<<BATCH / BPB, NT2>>>(
        x, b1, b2, b3, b4, f1b, f2b, f3b, f4w, f4b, out);
}